// round 1
// baseline (speedup 1.0000x reference)
#include <cuda_runtime.h>
#include <cuda_bf16.h>
#include <math.h>

// Problem constants
#define BB 2
#define SS 2048
#define DD 1024
#define RR 64
#define HH 16
#define DH 64
#define NN 32
#define BS (BB*SS)        // 4096
#define NR (NN*RR)        // 2048

// -------------------- scratch (device globals; no allocs allowed) --------------------
__device__ float g_Ft0[DD*NR];      // f_qk transposed [D, N*R]   8MB
__device__ float g_Ft1[DD*NR];      // f_v transposed             8MB
__device__ float g_P  [(size_t)BS*NR]; // projection buffer      32MB
__device__ float g_hq [BS*RR];
__device__ float g_hk [BS*RR];
__device__ float g_hv [BS*RR];
__device__ float g_HW [(size_t)BS*NR]; // HW buffer (reused)     32MB
__device__ float g_Q  [(size_t)BS*DD];
__device__ float g_K  [(size_t)BS*DD];
__device__ float g_V  [(size_t)BS*DD];
__device__ float g_AO [(size_t)BS*DD];
__device__ float g_WOt[DD*DD];

// -------------------- transpose bank: f[N][D][R] -> out[D][N*R] --------------------
__global__ void transpose_bank(const float* __restrict__ f, float* __restrict__ o) {
    int idx = blockIdx.x * 256 + threadIdx.x;     // over N*D*R = 2M
    int r = idx & (RR-1);
    int d = (idx >> 6) & (DD-1);
    int n = idx >> 16;
    o[(size_t)d*NR + n*RR + r] = f[idx];
}

// -------------------- transpose W_O: out[d][o] = in[o][d], 1024x1024 --------------------
__global__ void transpose_wo(const float* __restrict__ in, float* __restrict__ out) {
    __shared__ float t[32][33];
    int bx = blockIdx.x * 32, by = blockIdx.y * 32;
    int x = threadIdx.x, y = threadIdx.y;   // block (32,8)
    #pragma unroll
    for (int i = 0; i < 32; i += 8)
        t[y+i][x] = in[(size_t)(by+y+i)*DD + bx + x];
    __syncthreads();
    #pragma unroll
    for (int i = 0; i < 32; i += 8)
        out[(size_t)(bx+y+i)*DD + by + x] = t[x][y+i];
}

// -------------------- SGEMM: C[M,N] = A[M,K] @ B[K,N], row-major, 128x128x8 --------------------
__global__ __launch_bounds__(256, 2)
void sgemm128(const float* __restrict__ A, const float* __restrict__ B,
              float* __restrict__ C, int M, int N, int K)
{
    __shared__ float As[8][128];
    __shared__ float Bs[8][128];
    int tid = threadIdx.x;
    const float* Ab = A + (size_t)blockIdx.y * 128 * K;
    const float* Bb = B + (size_t)blockIdx.x * 128;
    float*       Cb = C + (size_t)blockIdx.y * 128 * N + blockIdx.x * 128;

    int arow = tid >> 1;              // 0..127
    int acol = (tid & 1) << 2;        // 0 or 4
    int brow = tid >> 5;              // 0..7
    int bcol = (tid & 31) << 2;       // 0..124
    int tr   = (tid >> 4) << 3;       // thread tile row0
    int tc   = (tid & 15) << 3;       // thread tile col0

    float acc[8][8] = {};

    float4 aReg = *(const float4*)(Ab + (size_t)arow*K + acol);
    float4 bReg = *(const float4*)(Bb + (size_t)brow*N + bcol);

    for (int k0 = 0; k0 < K; k0 += 8) {
        As[acol+0][arow] = aReg.x;
        As[acol+1][arow] = aReg.y;
        As[acol+2][arow] = aReg.z;
        As[acol+3][arow] = aReg.w;
        *(float4*)&Bs[brow][bcol] = bReg;
        __syncthreads();
        if (k0 + 8 < K) {
            aReg = *(const float4*)(Ab + (size_t)arow*K + (k0+8) + acol);
            bReg = *(const float4*)(Bb + (size_t)(k0+8+brow)*N + bcol);
        }
        #pragma unroll
        for (int kk = 0; kk < 8; kk++) {
            float ar[8], br[8];
            *(float4*)(ar)   = *(const float4*)&As[kk][tr];
            *(float4*)(ar+4) = *(const float4*)&As[kk][tr+4];
            *(float4*)(br)   = *(const float4*)&Bs[kk][tc];
            *(float4*)(br+4) = *(const float4*)&Bs[kk][tc+4];
            #pragma unroll
            for (int i = 0; i < 8; i++)
                #pragma unroll
                for (int j = 0; j < 8; j++)
                    acc[i][j] += ar[i] * br[j];
        }
        __syncthreads();
    }
    #pragma unroll
    for (int i = 0; i < 8; i++) {
        *(float4*)(Cb + (size_t)(tr+i)*N + tc)
            = make_float4(acc[i][0], acc[i][1], acc[i][2], acc[i][3]);
        *(float4*)(Cb + (size_t)(tr+i)*N + tc + 4)
            = make_float4(acc[i][4], acc[i][5], acc[i][6], acc[i][7]);
    }
}

// -------------------- h reductions --------------------
// hq[bs,r] = sum_n wQ[bs,n]*P[bs,n*R+r]; hk likewise (shared P reads)
__global__ void reduce_h2(const float* __restrict__ P,
                          const float* __restrict__ wQ, const float* __restrict__ wK,
                          float* __restrict__ hq, float* __restrict__ hk)
{
    int gid = blockIdx.x * 256 + threadIdx.x;   // over BS*R
    int bs = gid >> 6, r = gid & 63;
    const float* Pr = P + (size_t)bs*NR + r;
    const float* wq = wQ + bs*NN;
    const float* wk = wK + bs*NN;
    float aq = 0.f, ak = 0.f;
    #pragma unroll
    for (int n = 0; n < NN; n++) {
        float p = Pr[n*RR];
        aq += wq[n] * p;
        ak += wk[n] * p;
    }
    hq[gid] = aq; hk[gid] = ak;
}

__global__ void reduce_h1(const float* __restrict__ P, const float* __restrict__ w,
                          float* __restrict__ h)
{
    int gid = blockIdx.x * 256 + threadIdx.x;
    int bs = gid >> 6, r = gid & 63;
    const float* Pr = P + (size_t)bs*NR + r;
    const float* ww = w + bs*NN;
    float a = 0.f;
    #pragma unroll
    for (int n = 0; n < NN; n++) a += ww[n] * Pr[n*RR];
    h[gid] = a;
}

// -------------------- HW[bs, n*R+r] = h[bs,r]*w[bs,n] --------------------
__global__ void build_hw(const float* __restrict__ h, const float* __restrict__ w,
                         float* __restrict__ HW)
{
    size_t gid = (size_t)blockIdx.x * 256 + threadIdx.x;  // over BS*NR = 8.4M
    int bs = (int)(gid >> 11);
    int n  = (int)((gid >> 6) & 31);
    int r  = (int)(gid & 63);
    HW[gid] = h[bs*RR + r] * w[bs*NN + n];
}

// -------------------- causal flash attention, fp32, 64x64 tiles --------------------
// Q/K/V/AO layout: [bs = b*S+s, d = h*64+dh], row stride 1024.
__global__ __launch_bounds__(256)
void flash_fp32(const float* __restrict__ Qb, const float* __restrict__ Kb,
                const float* __restrict__ Vb, float* __restrict__ AO)
{
    extern __shared__ float sm[];
    float (*qT)[68] = (float(*)[68])(sm);             // [d][row], scaled
    float (*kT)[68] = (float(*)[68])(sm + 64*68);     // [d][col]; reused as pT[k][row]
    float (*vS)[68] = (float(*)[68])(sm + 2*64*68);   // [k][d]

    int tid = threadIdx.x;
    int tx = tid & 15, ty = tid >> 4;
    int qb = blockIdx.x;                 // query block 0..31
    int bh = blockIdx.y;                 // 0..31
    int b = bh >> 4, h = bh & 15;
    size_t base = (size_t)b * SS * DD + (size_t)h * DH;

    const float scale = 0.125f;          // 1/sqrt(64)
    // load Q tile (scaled) transposed: qT[d][row]
    for (int i = tid; i < 64*16; i += 256) {
        int row = i >> 4, j = i & 15;
        float4 q = *(const float4*)(Qb + base + (size_t)(qb*64 + row)*DD + j*4);
        qT[j*4+0][row] = q.x * scale;
        qT[j*4+1][row] = q.y * scale;
        qT[j*4+2][row] = q.z * scale;
        qT[j*4+3][row] = q.w * scale;
    }

    float o[4][4] = {};
    float m_i[4], l_i[4];
    #pragma unroll
    for (int i = 0; i < 4; i++) { m_i[i] = -3.0e38f; l_i[i] = 0.f; }

    for (int jb = 0; jb <= qb; jb++) {
        __syncthreads();   // previous-iter consumers done (and Q visible on iter 0)
        for (int i = tid; i < 64*16; i += 256) {
            int row = i >> 4, j = i & 15;
            float4 kv = *(const float4*)(Kb + base + (size_t)(jb*64 + row)*DD + j*4);
            kT[j*4+0][row] = kv.x; kT[j*4+1][row] = kv.y;
            kT[j*4+2][row] = kv.z; kT[j*4+3][row] = kv.w;
            float4 vv = *(const float4*)(Vb + base + (size_t)(jb*64 + row)*DD + j*4);
            *(float4*)&vS[row][j*4] = vv;
        }
        __syncthreads();

        // scores S = (Q*scale) K^T : rank-1 over d
        float s[4][4] = {};
        #pragma unroll 16
        for (int d = 0; d < 64; d++) {
            float4 a  = *(const float4*)&qT[d][ty*4];
            float4 bb = *(const float4*)&kT[d][tx*4];
            s[0][0] += a.x*bb.x; s[0][1] += a.x*bb.y; s[0][2] += a.x*bb.z; s[0][3] += a.x*bb.w;
            s[1][0] += a.y*bb.x; s[1][1] += a.y*bb.y; s[1][2] += a.y*bb.z; s[1][3] += a.y*bb.w;
            s[2][0] += a.z*bb.x; s[2][1] += a.z*bb.y; s[2][2] += a.z*bb.z; s[2][3] += a.z*bb.w;
            s[3][0] += a.w*bb.x; s[3][1] += a.w*bb.y; s[3][2] += a.w*bb.z; s[3][3] += a.w*bb.w;
        }
        if (jb == qb) {   // causal mask inside diagonal block
            #pragma unroll
            for (int i = 0; i < 4; i++)
                #pragma unroll
                for (int j = 0; j < 4; j++)
                    if (tx*4 + j > ty*4 + i) s[i][j] = -1.0e30f;
        }

        // online softmax
        #pragma unroll
        for (int i = 0; i < 4; i++) {
            float mt = fmaxf(fmaxf(s[i][0], s[i][1]), fmaxf(s[i][2], s[i][3]));
            #pragma unroll
            for (int off = 8; off > 0; off >>= 1)
                mt = fmaxf(mt, __shfl_xor_sync(0xffffffffu, mt, off, 16));
            float mn = fmaxf(m_i[i], mt);
            float alpha = __expf(m_i[i] - mn);
            m_i[i] = mn;
            float ls = 0.f;
            #pragma unroll
            for (int j = 0; j < 4; j++) {
                float p = __expf(s[i][j] - mn);
                s[i][j] = p;
                ls += p;
            }
            #pragma unroll
            for (int off = 8; off > 0; off >>= 1)
                ls += __shfl_xor_sync(0xffffffffu, ls, off, 16);
            l_i[i] = l_i[i] * alpha + ls;
            #pragma unroll
            for (int j = 0; j < 4; j++) o[i][j] *= alpha;
        }

        __syncthreads();   // all reads of kT done
        // write P transposed into kT storage: pT[k][row]
        #pragma unroll
        for (int i = 0; i < 4; i++)
            #pragma unroll
            for (int j = 0; j < 4; j++)
                kT[tx*4 + j][ty*4 + i] = s[i][j];
        __syncthreads();

        // O += P V : rank-1 over k
        #pragma unroll 16
        for (int k = 0; k < 64; k++) {
            float4 a  = *(const float4*)&kT[k][ty*4];
            float4 bv = *(const float4*)&vS[k][tx*4];
            o[0][0] += a.x*bv.x; o[0][1] += a.x*bv.y; o[0][2] += a.x*bv.z; o[0][3] += a.x*bv.w;
            o[1][0] += a.y*bv.x; o[1][1] += a.y*bv.y; o[1][2] += a.y*bv.z; o[1][3] += a.y*bv.w;
            o[2][0] += a.z*bv.x; o[2][1] += a.z*bv.y; o[2][2] += a.z*bv.z; o[2][3] += a.z*bv.w;
            o[3][0] += a.w*bv.x; o[3][1] += a.w*bv.y; o[3][2] += a.w*bv.z; o[3][3] += a.w*bv.w;
        }
    }

    // epilogue: normalize and store
    #pragma unroll
    for (int i = 0; i < 4; i++) {
        float inv = 1.0f / l_i[i];
        int row = qb*64 + ty*4 + i;
        float4 w = make_float4(o[i][0]*inv, o[i][1]*inv, o[i][2]*inv, o[i][3]*inv);
        *(float4*)(AO + base + (size_t)row*DD + tx*4) = w;
    }
}

// -------------------- launch --------------------
extern "C" void kernel_launch(void* const* d_in, const int* in_sizes, int n_in,
                              void* d_out, int out_size)
{
    const float* x     = (const float*)d_in[0];
    const float* wfqkQ = (const float*)d_in[1];
    const float* wfqkK = (const float*)d_in[2];
    const float* wfv   = (const float*)d_in[3];
    const float* wrqkQ = (const float*)d_in[4];
    const float* wrqkK = (const float*)d_in[5];
    const float* wrv   = (const float*)d_in[6];
    const float* f_qk  = (const float*)d_in[7];
    const float* f_v   = (const float*)d_in[8];
    const float* r_qk  = (const float*)d_in[9];
    const float* r_v   = (const float*)d_in[10];
    const float* W_O   = (const float*)d_in[11];
    float* out = (float*)d_out;

    float *Ft0, *Ft1, *P, *hq, *hk, *hv, *HW, *Qb, *Kb, *Vb, *AO, *WOt;
    cudaGetSymbolAddress((void**)&Ft0, g_Ft0);
    cudaGetSymbolAddress((void**)&Ft1, g_Ft1);
    cudaGetSymbolAddress((void**)&P,   g_P);
    cudaGetSymbolAddress((void**)&hq,  g_hq);
    cudaGetSymbolAddress((void**)&hk,  g_hk);
    cudaGetSymbolAddress((void**)&hv,  g_hv);
    cudaGetSymbolAddress((void**)&HW,  g_HW);
    cudaGetSymbolAddress((void**)&Qb,  g_Q);
    cudaGetSymbolAddress((void**)&Kb,  g_K);
    cudaGetSymbolAddress((void**)&Vb,  g_V);
    cudaGetSymbolAddress((void**)&AO,  g_AO);
    cudaGetSymbolAddress((void**)&WOt, g_WOt);

    // 1) transposes
    transpose_bank<<<(NN*DD*RR)/256, 256>>>(f_qk, Ft0);
    transpose_bank<<<(NN*DD*RR)/256, 256>>>(f_v,  Ft1);
    transpose_wo<<<dim3(32, 32), dim3(32, 8)>>>(W_O, WOt);

    // 2) projection GEMMs + reductions
    sgemm128<<<dim3(NR/128, BS/128), 256>>>(x, Ft0, P, BS, NR, DD);
    reduce_h2<<<(BS*RR)/256, 256>>>(P, wfqkQ, wfqkK, hq, hk);
    sgemm128<<<dim3(NR/128, BS/128), 256>>>(x, Ft1, P, BS, NR, DD);
    reduce_h1<<<(BS*RR)/256, 256>>>(P, wfv, hv);

    // 3) restore GEMMs (HW buffer reused; stream-ordered)
    build_hw<<<(unsigned)(((size_t)BS*NR)/256), 256>>>(hq, wrqkQ, HW);
    sgemm128<<<dim3(DD/128, BS/128), 256>>>(HW, r_qk, Qb, BS, DD, NR);
    build_hw<<<(unsigned)(((size_t)BS*NR)/256), 256>>>(hk, wrqkK, HW);
    sgemm128<<<dim3(DD/128, BS/128), 256>>>(HW, r_qk, Kb, BS, DD, NR);
    build_hw<<<(unsigned)(((size_t)BS*NR)/256), 256>>>(hv, wrv, HW);
    sgemm128<<<dim3(DD/128, BS/128), 256>>>(HW, r_v, Vb, BS, DD, NR);

    // 4) causal attention
    int smem = 3 * 64 * 68 * sizeof(float);   // 52224
    cudaFuncSetAttribute(flash_fp32, cudaFuncAttributeMaxDynamicSharedMemorySize, smem);
    flash_fp32<<<dim3(SS/64, BB*HH), 256, smem>>>(Qb, Kb, Vb, AO);

    // 5) output projection
    sgemm128<<<dim3(DD/128, BS/128), 256>>>(AO, WOt, out, BS, DD, DD);
}

// round 4
// speedup vs baseline: 1.5562x; 1.5562x over previous
#include <cuda_runtime.h>
#include <cuda_bf16.h>
#include <stdint.h>
#include <math.h>

// Problem constants
#define BB 2
#define SS 2048
#define DD 1024
#define RR 64
#define HH 16
#define DH 64
#define NN 32
#define BS (BB*SS)        // 4096
#define NR (NN*RR)        // 2048

// ===================== PTX helpers (compute_103-safe: sm_80 era) =====================
__device__ __forceinline__ uint32_t smem_u32(const void* p) {
    uint32_t a;
    asm("{ .reg .u64 t; cvta.to.shared.u64 t, %1; cvt.u32.u64 %0, t; }" : "=r"(a) : "l"(p));
    return a;
}
__device__ __forceinline__ void cp16(uint32_t saddr, const void* g) {
    asm volatile("cp.async.cg.shared.global [%0], [%1], 16;" :: "r"(saddr), "l"(g) : "memory");
}
#define CP_COMMIT() asm volatile("cp.async.commit_group;" ::: "memory")
#define CP_WAIT1()  asm volatile("cp.async.wait_group 1;" ::: "memory")
#define CP_WAIT0()  asm volatile("cp.async.wait_group 0;" ::: "memory")

#define LDSM4(r0, r1, r2, r3, addr) \
    asm volatile("ldmatrix.sync.aligned.m8n8.x4.shared.b16 {%0,%1,%2,%3}, [%4];" \
        : "=r"(r0), "=r"(r1), "=r"(r2), "=r"(r3) : "r"(addr))

#define MMA16816(d, a, b) \
    asm volatile("mma.sync.aligned.m16n8k16.row.col.f32.bf16.bf16.f32 " \
        "{%0,%1,%2,%3}, {%4,%5,%6,%7}, {%8,%9}, {%0,%1,%2,%3};" \
        : "+f"((d)[0]), "+f"((d)[1]), "+f"((d)[2]), "+f"((d)[3]) \
        : "r"((a)[0]), "r"((a)[1]), "r"((a)[2]), "r"((a)[3]), "r"((b)[0]), "r"((b)[1]))

// ===================== scratch (device globals) =====================
__device__ __align__(256) __nv_bfloat16 g_Xcat [(size_t)BS * 6144];      // X split-3  (A3)
__device__ __align__(256) __nv_bfloat16 g_Fcat [(size_t)NR * 6144];      // f_qk^T split-3 (B3)
__device__ __align__(256) __nv_bfloat16 g_Fvcat[(size_t)NR * 3072];      // f_v^T split-2 (B2)
__device__ __align__(256) __nv_bfloat16 g_HWcat[(size_t)2 * BS * 12288]; // HW q|k split-3
__device__ __align__(256) __nv_bfloat16 g_Rcat [(size_t)DD * 12288];     // r_qk^T split-3 (B3)
__device__ __align__(256) __nv_bfloat16 g_Rvcat[(size_t)DD * 6144];      // r_v^T split-2 (B2)
__device__ __align__(256) __nv_bfloat16 g_WOcat[(size_t)DD * 3072];      // W_O split-2 (B2)
__device__ __align__(256) __nv_bfloat16 g_AOcat[(size_t)BS * 3072];      // AO split-2 (A2)
__device__ float g_P  [(size_t)BS * NR];
__device__ float g_hq [BS * RR];
__device__ float g_hk [BS * RR];
__device__ float g_hv [BS * RR];
__device__ float g_QK [(size_t)2 * BS * DD];  // Q rows 0..4095, K rows 4096..8191
__device__ float g_V  [(size_t)BS * DD];
__device__ float g_AO [(size_t)BS * DD];

// ===================== split helpers =====================
__device__ __forceinline__ void split3f(float x, __nv_bfloat16& h, __nv_bfloat16& m, __nv_bfloat16& l) {
    h = __float2bfloat16_rn(x);
    float r = x - __bfloat162float(h);
    m = __float2bfloat16_rn(r);
    r -= __bfloat162float(m);
    l = __float2bfloat16_rn(r);
}

// X[4096,1024] -> Xcat[4096,6144], A3 pattern {h,h,m,h,l,m}  (prefix {h,h,m} = A2)
__global__ void conv_x3(const float* __restrict__ in, __nv_bfloat16* __restrict__ out) {
    size_t gid = (size_t)blockIdx.x * 256 + threadIdx.x;  // BS*DD
    size_t row = gid >> 10; int col = (int)(gid & 1023);
    __nv_bfloat16 h, m, l; split3f(in[gid], h, m, l);
    __nv_bfloat16* o = out + row * 6144 + col;
    o[0] = h; o[1024] = h; o[2048] = m; o[3072] = h; o[4096] = l; o[5120] = m;
}

// f[N][D][R] -> Fcat[nr][6*1024], B3 pattern {h,m,h,l,h,m}
__global__ void conv_f3(const float* __restrict__ f, __nv_bfloat16* __restrict__ out) {
    size_t gid = (size_t)blockIdx.x * 256 + threadIdx.x;   // NR*DD
    int nr = (int)(gid >> 10), d = (int)(gid & 1023);
    int n = nr >> 6, r = nr & 63;
    __nv_bfloat16 h, m, l; split3f(f[((size_t)n << 16) + (d << 6) + r], h, m, l);
    __nv_bfloat16* o = out + (size_t)nr * 6144 + d;
    o[0] = h; o[1024] = m; o[2048] = h; o[3072] = l; o[4096] = h; o[5120] = m;
}
// f_v -> Fvcat[nr][3*1024], B2 pattern {h,m,h}
__global__ void conv_f2(const float* __restrict__ f, __nv_bfloat16* __restrict__ out) {
    size_t gid = (size_t)blockIdx.x * 256 + threadIdx.x;
    int nr = (int)(gid >> 10), d = (int)(gid & 1023);
    int n = nr >> 6, r = nr & 63;
    __nv_bfloat16 h, m, l; split3f(f[((size_t)n << 16) + (d << 6) + r], h, m, l);
    __nv_bfloat16* o = out + (size_t)nr * 3072 + d;
    o[0] = h; o[1024] = m; o[2048] = h;
}

// r_qk[N][R][D] -> Rcat[d][6*2048], B3
__global__ void conv_r3(const float* __restrict__ rk, __nv_bfloat16* __restrict__ out) {
    size_t gid = (size_t)blockIdx.x * 256 + threadIdx.x;   // DD*NR
    int d = (int)(gid >> 11), nr = (int)(gid & 2047);
    int n = nr >> 6, r = nr & 63;
    __nv_bfloat16 h, m, l; split3f(rk[((size_t)n << 16) + (r << 10) + d], h, m, l);
    __nv_bfloat16* o = out + (size_t)d * 12288 + nr;
    o[0] = h; o[2048] = m; o[4096] = h; o[6144] = l; o[8192] = h; o[10240] = m;
}
// r_v -> Rvcat[d][3*2048], B2
__global__ void conv_r2(const float* __restrict__ rv, __nv_bfloat16* __restrict__ out) {
    size_t gid = (size_t)blockIdx.x * 256 + threadIdx.x;
    int d = (int)(gid >> 11), nr = (int)(gid & 2047);
    int n = nr >> 6, r = nr & 63;
    __nv_bfloat16 h, m, l; split3f(rv[((size_t)n << 16) + (r << 10) + d], h, m, l);
    __nv_bfloat16* o = out + (size_t)d * 6144 + nr;
    o[0] = h; o[2048] = m; o[4096] = h;
}

// W_O[out,in] is already [N,K] -> WOcat[1024][3*1024], B2
__global__ void conv_wo2(const float* __restrict__ w, __nv_bfloat16* __restrict__ out) {
    size_t gid = (size_t)blockIdx.x * 256 + threadIdx.x;  // DD*DD
    size_t row = gid >> 10; int col = (int)(gid & 1023);
    __nv_bfloat16 h, m, l; split3f(w[gid], h, m, l);
    __nv_bfloat16* o = out + row * 3072 + col;
    o[0] = h; o[1024] = m; o[2048] = h;
}

// AO[4096,1024] -> AOcat[4096,3072], A2 pattern {h,h,m}
__global__ void conv_ao2(const float* __restrict__ in, __nv_bfloat16* __restrict__ out) {
    size_t gid = (size_t)blockIdx.x * 256 + threadIdx.x;
    size_t row = gid >> 10; int col = (int)(gid & 1023);
    __nv_bfloat16 h, m, l; split3f(in[gid], h, m, l);
    __nv_bfloat16* o = out + row * 3072 + col;
    o[0] = h; o[1024] = h; o[2048] = m;
}

// HW split-3: out[bs][6*2048], A3 {h,h,m,h,l,m}; p = h[bs,r]*w[bs,n]
__global__ void build_hw3(const float* __restrict__ hbuf, const float* __restrict__ w,
                          __nv_bfloat16* __restrict__ out) {
    size_t gid = (size_t)blockIdx.x * 256 + threadIdx.x;   // BS*NR
    int bs = (int)(gid >> 11), nr = (int)(gid & 2047);
    int n = nr >> 6, r = nr & 63;
    float p = hbuf[bs * RR + r] * w[bs * NN + n];
    __nv_bfloat16 h, m, l; split3f(p, h, m, l);
    __nv_bfloat16* o = out + (size_t)bs * 12288 + nr;
    o[0] = h; o[2048] = h; o[4096] = m; o[6144] = h; o[8192] = l; o[10240] = m;
}
// HW split-2: out[bs][3*2048], A2 {h,h,m}
__global__ void build_hw2(const float* __restrict__ hbuf, const float* __restrict__ w,
                          __nv_bfloat16* __restrict__ out) {
    size_t gid = (size_t)blockIdx.x * 256 + threadIdx.x;
    int bs = (int)(gid >> 11), nr = (int)(gid & 2047);
    int n = nr >> 6, r = nr & 63;
    float p = hbuf[bs * RR + r] * w[bs * NN + n];
    __nv_bfloat16 h, m, l; split3f(p, h, m, l);
    __nv_bfloat16* o = out + (size_t)bs * 6144 + nr;
    o[0] = h; o[2048] = h; o[4096] = m;
}

// ===================== h reductions (P fp32) =====================
__global__ void reduce_h2(const float* __restrict__ P,
                          const float* __restrict__ wQ, const float* __restrict__ wK,
                          float* __restrict__ hq, float* __restrict__ hk) {
    int gid = blockIdx.x * 256 + threadIdx.x;   // BS*RR
    int bs = gid >> 6, r = gid & 63;
    const float* Pr = P + (size_t)bs * NR + r;
    const float* wq = wQ + bs * NN;
    const float* wk = wK + bs * NN;
    float aq = 0.f, ak = 0.f;
    #pragma unroll
    for (int n = 0; n < NN; n++) {
        float p = Pr[n * RR];
        aq += wq[n] * p;
        ak += wk[n] * p;
    }
    hq[gid] = aq; hk[gid] = ak;
}
__global__ void reduce_h1(const float* __restrict__ P, const float* __restrict__ w,
                          float* __restrict__ h) {
    int gid = blockIdx.x * 256 + threadIdx.x;
    int bs = gid >> 6, r = gid & 63;
    const float* Pr = P + (size_t)bs * NR + r;
    const float* ww = w + bs * NN;
    float a = 0.f;
    #pragma unroll
    for (int n = 0; n < NN; n++) a += ww[n] * Pr[n * RR];
    h[gid] = a;
}

// ===================== bf16 mma.sync GEMM =====================
// C[M,N] fp32 = A[M,K'] (bf16 K-major) @ B[N,K']^T (bf16 K-major)
// Block 128x128, BK=64 (128B rows, XOR swizzle), 8 warps (2x4) of 64x32.
// Double-buffered cp.async.
#define TG_SMEM 65536

__device__ __forceinline__ void tg_issue(uint32_t sAb, uint32_t sBb,
                                         const __nv_bfloat16* ag, const __nv_bfloat16* bg,
                                         size_t lda, size_t ldb, int ldrow, int ldc8)
{
    #pragma unroll
    for (int i = 0; i < 4; i++) {
        int row = ldrow + i * 32;
        uint32_t ph = (uint32_t)(ldc8 ^ (row & 7));
        cp16(sAb + row * 128 + ph * 16, ag + (size_t)row * lda);
    }
    #pragma unroll
    for (int i = 0; i < 4; i++) {
        int row = ldrow + i * 32;
        uint32_t ph = (uint32_t)(ldc8 ^ (row & 7));
        cp16(sBb + row * 128 + ph * 16, bg + (size_t)row * ldb);
    }
    CP_COMMIT();
}

__global__ __launch_bounds__(256, 2)
void tgemm(const __nv_bfloat16* __restrict__ A, const __nv_bfloat16* __restrict__ B,
           float* __restrict__ C, int lda_i, int ldb_i, int ldc_i, int T)
{
    extern __shared__ char sm[];
    uint32_t sbase = smem_u32(sm);
    int tid = threadIdx.x, wid = tid >> 5, lane = tid & 31;
    int warp_m = wid & 1, warp_n = wid >> 1;    // 2 x 4
    size_t lda = (size_t)lda_i, ldb = (size_t)ldb_i, ldc = (size_t)ldc_i;
    const __nv_bfloat16* Ab = A + (size_t)blockIdx.y * 128 * lda;
    const __nv_bfloat16* Bb = B + (size_t)blockIdx.x * 128 * ldb;

    uint32_t sA[2] = { sbase,         sbase + 32768 };
    uint32_t sB[2] = { sbase + 16384, sbase + 49152 };

    int ldrow = tid >> 3;       // 0..31
    int ldc8  = tid & 7;        // 16B chunk within 128B row

    // ldmatrix lane geometry
    int g  = lane >> 3, lr = lane & 7;
    int arow0 = warp_m * 64 + (g & 1) * 8 + lr;   // + mt*16
    int ac    = g >> 1;                            // k8-half
    int brow0 = warp_n * 32 + (g >> 1) * 8 + lr;  // + np*16
    int bc    = g & 1;

    // prologue: stages 0,1
    tg_issue(sA[0], sB[0], Ab + ldc8 * 8, Bb + ldc8 * 8, lda, ldb, ldrow, ldc8);
    tg_issue(sA[1], sB[1], Ab + 64 + ldc8 * 8, Bb + 64 + ldc8 * 8, lda, ldb, ldrow, ldc8);

    float acc[4][4][4] = {};

    for (int kt = 0; kt < T; kt++) {
        if (kt + 1 < T) { CP_WAIT1(); } else { CP_WAIT0(); }
        __syncthreads();
        int buf = kt & 1;
        uint32_t sAb = sA[buf], sBb = sB[buf];

        #pragma unroll
        for (int ks = 0; ks < 4; ks++) {
            uint32_t af[4][4];
            #pragma unroll
            for (int mt = 0; mt < 4; mt++) {
                int row = arow0 + mt * 16;
                uint32_t ph = (uint32_t)((2 * ks + ac) ^ (arow0 & 7));
                LDSM4(af[mt][0], af[mt][1], af[mt][2], af[mt][3], sAb + row * 128 + ph * 16);
            }
            uint32_t bf[4][2];
            #pragma unroll
            for (int np = 0; np < 2; np++) {
                int row = brow0 + np * 16;
                uint32_t ph = (uint32_t)((2 * ks + bc) ^ (brow0 & 7));
                uint32_t r0, r1, r2, r3;
                LDSM4(r0, r1, r2, r3, sBb + row * 128 + ph * 16);
                bf[2*np][0] = r0; bf[2*np][1] = r1;
                bf[2*np+1][0] = r2; bf[2*np+1][1] = r3;
            }
            #pragma unroll
            for (int mt = 0; mt < 4; mt++)
                #pragma unroll
                for (int nt = 0; nt < 4; nt++)
                    MMA16816(acc[mt][nt], af[mt], bf[nt]);
        }
        __syncthreads();
        if (kt + 2 < T)
            tg_issue(sA[buf], sB[buf],
                     Ab + (size_t)(kt + 2) * 64 + ldc8 * 8,
                     Bb + (size_t)(kt + 2) * 64 + ldc8 * 8, lda, ldb, ldrow, ldc8);
    }

    // epilogue
    int crow = blockIdx.y * 128 + warp_m * 64 + (lane >> 2);
    int ccol = blockIdx.x * 128 + warp_n * 32 + (lane & 3) * 2;
    #pragma unroll
    for (int mt = 0; mt < 4; mt++) {
        #pragma unroll
        for (int nt = 0; nt < 4; nt++) {
            float* p = C + (size_t)(crow + mt * 16) * ldc + ccol + nt * 8;
            p[0] = acc[mt][nt][0]; p[1] = acc[mt][nt][1];
            float* p2 = p + 8 * ldc;
            p2[0] = acc[mt][nt][2]; p2[1] = acc[mt][nt][3];
        }
    }
}

// ===================== causal flash attention (fp32) =====================
__global__ __launch_bounds__(256)
void flash_fp32(const float* __restrict__ Qb, const float* __restrict__ Kb,
                const float* __restrict__ Vb, float* __restrict__ AO)
{
    extern __shared__ float smf[];
    float (*qT)[68] = (float(*)[68])(smf);
    float (*kT)[68] = (float(*)[68])(smf + 64*68);
    float (*vS)[68] = (float(*)[68])(smf + 2*64*68);

    int tid = threadIdx.x;
    int tx = tid & 15, ty = tid >> 4;
    int qb = blockIdx.x;
    int bh = blockIdx.y;
    int b = bh >> 4, h = bh & 15;
    size_t base = (size_t)b * SS * DD + (size_t)h * DH;

    const float scale = 0.125f;
    for (int i = tid; i < 64*16; i += 256) {
        int row = i >> 4, j = i & 15;
        float4 q = *(const float4*)(Qb + base + (size_t)(qb*64 + row)*DD + j*4);
        qT[j*4+0][row] = q.x * scale;
        qT[j*4+1][row] = q.y * scale;
        qT[j*4+2][row] = q.z * scale;
        qT[j*4+3][row] = q.w * scale;
    }

    float o[4][4] = {};
    float m_i[4], l_i[4];
    #pragma unroll
    for (int i = 0; i < 4; i++) { m_i[i] = -3.0e38f; l_i[i] = 0.f; }

    for (int jb = 0; jb <= qb; jb++) {
        __syncthreads();
        for (int i = tid; i < 64*16; i += 256) {
            int row = i >> 4, j = i & 15;
            float4 kv = *(const float4*)(Kb + base + (size_t)(jb*64 + row)*DD + j*4);
            kT[j*4+0][row] = kv.x; kT[j*4+1][row] = kv.y;
            kT[j*4+2][row] = kv.z; kT[j*4+3][row] = kv.w;
            float4 vv = *(const float4*)(Vb + base + (size_t)(jb*64 + row)*DD + j*4);
            *(float4*)&vS[row][j*4] = vv;
        }
        __syncthreads();

        float s[4][4] = {};
        #pragma unroll 16
        for (int d = 0; d < 64; d++) {
            float4 a  = *(const float4*)&qT[d][ty*4];
            float4 bb = *(const float4*)&kT[d][tx*4];
            s[0][0] += a.x*bb.x; s[0][1] += a.x*bb.y; s[0][2] += a.x*bb.z; s[0][3] += a.x*bb.w;
            s[1][0] += a.y*bb.x; s[1][1] += a.y*bb.y; s[1][2] += a.y*bb.z; s[1][3] += a.y*bb.w;
            s[2][0] += a.z*bb.x; s[2][1] += a.z*bb.y; s[2][2] += a.z*bb.z; s[2][3] += a.z*bb.w;
            s[3][0] += a.w*bb.x; s[3][1] += a.w*bb.y; s[3][2] += a.w*bb.z; s[3][3] += a.w*bb.w;
        }
        if (jb == qb) {
            #pragma unroll
            for (int i = 0; i < 4; i++)
                #pragma unroll
                for (int j = 0; j < 4; j++)
                    if (tx*4 + j > ty*4 + i) s[i][j] = -1.0e30f;
        }

        #pragma unroll
        for (int i = 0; i < 4; i++) {
            float mt = fmaxf(fmaxf(s[i][0], s[i][1]), fmaxf(s[i][2], s[i][3]));
            #pragma unroll
            for (int off = 8; off > 0; off >>= 1)
                mt = fmaxf(mt, __shfl_xor_sync(0xffffffffu, mt, off, 16));
            float mn = fmaxf(m_i[i], mt);
            float alpha = __expf(m_i[i] - mn);
            m_i[i] = mn;
            float ls = 0.f;
            #pragma unroll
            for (int j = 0; j < 4; j++) {
                float p = __expf(s[i][j] - mn);
                s[i][j] = p;
                ls += p;
            }
            #pragma unroll
            for (int off = 8; off > 0; off >>= 1)
                ls += __shfl_xor_sync(0xffffffffu, ls, off, 16);
            l_i[i] = l_i[i] * alpha + ls;
            #pragma unroll
            for (int j = 0; j < 4; j++) o[i][j] *= alpha;
        }

        __syncthreads();
        #pragma unroll
        for (int i = 0; i < 4; i++)
            #pragma unroll
            for (int j = 0; j < 4; j++)
                kT[tx*4 + j][ty*4 + i] = s[i][j];
        __syncthreads();

        #pragma unroll 16
        for (int k = 0; k < 64; k++) {
            float4 a  = *(const float4*)&kT[k][ty*4];
            float4 bv = *(const float4*)&vS[k][tx*4];
            o[0][0] += a.x*bv.x; o[0][1] += a.x*bv.y; o[0][2] += a.x*bv.z; o[0][3] += a.x*bv.w;
            o[1][0] += a.y*bv.x; o[1][1] += a.y*bv.y; o[1][2] += a.y*bv.z; o[1][3] += a.y*bv.w;
            o[2][0] += a.z*bv.x; o[2][1] += a.z*bv.y; o[2][2] += a.z*bv.z; o[2][3] += a.z*bv.w;
            o[3][0] += a.w*bv.x; o[3][1] += a.w*bv.y; o[3][2] += a.w*bv.z; o[3][3] += a.w*bv.w;
        }
    }

    #pragma unroll
    for (int i = 0; i < 4; i++) {
        float inv = 1.0f / l_i[i];
        int row = qb*64 + ty*4 + i;
        float4 w = make_float4(o[i][0]*inv, o[i][1]*inv, o[i][2]*inv, o[i][3]*inv);
        *(float4*)(AO + base + (size_t)row*DD + tx*4) = w;
    }
}

// ===================== launch =====================
extern "C" void kernel_launch(void* const* d_in, const int* in_sizes, int n_in,
                              void* d_out, int out_size)
{
    const float* x     = (const float*)d_in[0];
    const float* wfqkQ = (const float*)d_in[1];
    const float* wfqkK = (const float*)d_in[2];
    const float* wfv   = (const float*)d_in[3];
    const float* wrqkQ = (const float*)d_in[4];
    const float* wrqkK = (const float*)d_in[5];
    const float* wrv   = (const float*)d_in[6];
    const float* f_qk  = (const float*)d_in[7];
    const float* f_v   = (const float*)d_in[8];
    const float* r_qk  = (const float*)d_in[9];
    const float* r_v   = (const float*)d_in[10];
    const float* W_O   = (const float*)d_in[11];
    float* out = (float*)d_out;

    __nv_bfloat16 *Xcat, *Fcat, *Fvcat, *HWcat, *Rcat, *Rvcat, *WOcat, *AOcat;
    float *P, *hq, *hk, *hv, *QK, *V, *AO;
    cudaGetSymbolAddress((void**)&Xcat,  g_Xcat);
    cudaGetSymbolAddress((void**)&Fcat,  g_Fcat);
    cudaGetSymbolAddress((void**)&Fvcat, g_Fvcat);
    cudaGetSymbolAddress((void**)&HWcat, g_HWcat);
    cudaGetSymbolAddress((void**)&Rcat,  g_Rcat);
    cudaGetSymbolAddress((void**)&Rvcat, g_Rvcat);
    cudaGetSymbolAddress((void**)&WOcat, g_WOcat);
    cudaGetSymbolAddress((void**)&AOcat, g_AOcat);
    cudaGetSymbolAddress((void**)&P,  g_P);
    cudaGetSymbolAddress((void**)&hq, g_hq);
    cudaGetSymbolAddress((void**)&hk, g_hk);
    cudaGetSymbolAddress((void**)&hv, g_hv);
    cudaGetSymbolAddress((void**)&QK, g_QK);
    cudaGetSymbolAddress((void**)&V,  g_V);
    cudaGetSymbolAddress((void**)&AO, g_AO);

    cudaFuncSetAttribute(tgemm, cudaFuncAttributeMaxDynamicSharedMemorySize, TG_SMEM);
    cudaFuncSetAttribute(flash_fp32, cudaFuncAttributeMaxDynamicSharedMemorySize,
                         3 * 64 * 68 * (int)sizeof(float));

    // ---- conversions (operand prep) ----
    conv_x3 <<<(BS*DD)/256, 256>>>(x, Xcat);
    conv_f3 <<<(NR*DD)/256, 256>>>(f_qk, Fcat);
    conv_f2 <<<(NR*DD)/256, 256>>>(f_v,  Fvcat);
    conv_r3 <<<(DD*NR)/256, 256>>>(r_qk, Rcat);
    conv_r2 <<<(DD*NR)/256, 256>>>(r_v,  Rvcat);
    conv_wo2<<<(DD*DD)/256, 256>>>(W_O,  WOcat);

    // ---- projection: P = X @ f_qk^T (split-3), then h reductions ----
    tgemm<<<dim3(NR/128, BS/128), 256, TG_SMEM>>>(Xcat, Fcat, P, 6144, 6144, NR, 96);
    reduce_h2<<<(BS*RR)/256, 256>>>(P, wfqkQ, wfqkK, hq, hk);
    // NOTE: Xcat row stride is 6144; its 3072-col prefix {h,h,m} is the A2 pattern.
    tgemm<<<dim3(NR/128, BS/128), 256, TG_SMEM>>>(Xcat, Fvcat, P, 6144, 3072, NR, 48);
    reduce_h1<<<(BS*RR)/256, 256>>>(P, wfv, hv);

    // ---- restore: Q and K batched as one M=8192 GEMM ----
    build_hw3<<<(BS*NR)/256, 256>>>(hq, wrqkQ, HWcat);
    build_hw3<<<(BS*NR)/256, 256>>>(hk, wrqkK, HWcat + (size_t)BS * 12288);
    tgemm<<<dim3(DD/128, (2*BS)/128), 256, TG_SMEM>>>(HWcat, Rcat, QK, 12288, 12288, DD, 192);
    build_hw2<<<(BS*NR)/256, 256>>>(hv, wrv, HWcat);
    tgemm<<<dim3(DD/128, BS/128), 256, TG_SMEM>>>(HWcat, Rvcat, V, 6144, 6144, DD, 96);

    // ---- attention ----
    int fl_smem = 3 * 64 * 68 * (int)sizeof(float);
    flash_fp32<<<dim3(SS/64, BB*HH), 256, fl_smem>>>(QK, QK + (size_t)BS * DD, V, AO);

    // ---- output projection ----
    conv_ao2<<<(BS*DD)/256, 256>>>(AO, AOcat);
    tgemm<<<dim3(DD/128, BS/128), 256, TG_SMEM>>>(AOcat, WOcat, out, 3072, 3072, DD, 48);
}